// round 4
// baseline (speedup 1.0000x reference)
#include <cuda_runtime.h>
#include <math.h>
#include <stdint.h>

#define BB    32
#define NN    4096
#define NPQ   512
#define NSAMP 16
#define CC    256
#define HIDC  128
#define NPIX  (BB*NPQ*NSAMP)   /* 262144 */
#define NPTS  (BB*NN)          /* 131072 */

#define OUT_XYZ  0
#define OUT_FEAT (BB*NPQ*3)                  /* 49152 */
#define OUT_INDS (OUT_FEAT + BB*HIDC*NPQ)    /* 2146304 */

// ------------- static scratch (no allocations) -------------
__device__ float  g_PF[(size_t)NPTS*HIDC];    // per-point conv1 feature part
__device__ float  g_Y1[(size_t)NPIX*HIDC];    // activations ping
__device__ float  g_Y2[(size_t)NPIX*HIDC];    // activations pong
__device__ int    g_idx[NPIX];
__device__ float  g_gxyz[(size_t)NPIX*3];
__device__ double g_stats[3*2*HIDC];
__device__ float  g_bn[3*3*HIDC];
__device__ float  g_W1f[HIDC*CC];             // packed W1 feature part [o][k]

#define MMA8(c, a, b) asm volatile( \
  "mma.sync.aligned.m16n8k8.row.col.f32.tf32.tf32.f32 " \
  "{%0,%1,%2,%3}, {%4,%5,%6,%7}, {%8,%9}, {%0,%1,%2,%3};" \
  : "+f"((c)[0]), "+f"((c)[1]), "+f"((c)[2]), "+f"((c)[3]) \
  : "r"((a)[0]), "r"((a)[1]), "r"((a)[2]), "r"((a)[3]), "r"((b)[0]), "r"((b)[1]))

// ---------------------------------------------------------------------------
__global__ void zero_stats_kernel() {
    int i = blockIdx.x*256 + threadIdx.x;
    if (i < 3*2*HIDC) g_stats[i] = 0.0;
}

__global__ void prep_w1_kernel(const float* __restrict__ w1) {
    int o = blockIdx.x, k = threadIdx.x;
    g_W1f[o*CC + k] = w1[o*(CC+3) + 3 + k];
}

// ---------------------------------------------------------------------------
// FPS: one block per batch, 1024 threads, 4 points each. ONE barrier/iter.
// Bit-exact distance: ((dx*dx + dy*dy) + dz*dz) with rn ops (no FMA).
__global__ __launch_bounds__(1024) void fps_kernel(
    const float* __restrict__ seed, const float* __restrict__ xyz,
    float* __restrict__ out)
{
    int b = blockIdx.x;
    int t = threadIdx.x;
    int lane = t & 31, wid = t >> 5;
    __shared__ float s_cv[2][32], s_cx[2][32], s_cy[2][32], s_cz[2][32];
    __shared__ int   s_ci[2][32];
    __shared__ int   s_inds[NPQ];

    const float* sb = seed + (size_t)b*NN*3;
    float px[4], py[4], pz[4], dist[4];
#pragma unroll
    for (int j = 0; j < 4; j++) {
        int i = t + j*1024;
        px[j] = sb[i*3+0];
        py[j] = sb[i*3+1];
        pz[j] = sb[i*3+2];
        dist[j] = 1e10f;
    }
    if (t == 0) s_inds[0] = 0;
    // coordinates of point 0 (broadcast load)
    float lx = sb[0], ly = sb[1], lz = sb[2];

    for (int it = 1; it < NPQ; ++it) {
        float bv = -1.0f; int bi = 0;
        float bx = 0.f, by = 0.f, bz = 0.f;
#pragma unroll
        for (int j = 0; j < 4; j++) {
            float dx = __fadd_rn(px[j], -lx);
            float dy = __fadd_rn(py[j], -ly);
            float dz = __fadd_rn(pz[j], -lz);
            float d  = __fadd_rn(__fadd_rn(__fmul_rn(dx,dx), __fmul_rn(dy,dy)),
                                 __fmul_rn(dz,dz));
            dist[j] = fminf(dist[j], d);
            if (dist[j] > bv) { bv = dist[j]; bi = t + j*1024;
                                bx = px[j]; by = py[j]; bz = pz[j]; }
        }
        // warp butterfly reduce: max value, smallest index on ties, carry coords
#pragma unroll
        for (int off = 16; off > 0; off >>= 1) {
            float ov = __shfl_xor_sync(0xffffffffu, bv, off);
            int   oi = __shfl_xor_sync(0xffffffffu, bi, off);
            float ox = __shfl_xor_sync(0xffffffffu, bx, off);
            float oy = __shfl_xor_sync(0xffffffffu, by, off);
            float oz = __shfl_xor_sync(0xffffffffu, bz, off);
            if (ov > bv || (ov == bv && oi < bi)) {
                bv = ov; bi = oi; bx = ox; by = oy; bz = oz;
            }
        }
        int buf = it & 1;
        if (lane == 0) {
            s_cv[buf][wid] = bv; s_ci[buf][wid] = bi;
            s_cx[buf][wid] = bx; s_cy[buf][wid] = by; s_cz[buf][wid] = bz;
        }
        __syncthreads();
        // every warp redundantly reduces the 32 candidates (no 2nd barrier;
        // parity double-buffering protects slots across iterations)
        float v  = s_cv[buf][lane];
        int   ci = s_ci[buf][lane];
        int   sl = lane;
#pragma unroll
        for (int off = 16; off > 0; off >>= 1) {
            float ov = __shfl_xor_sync(0xffffffffu, v,  off);
            int   oi = __shfl_xor_sync(0xffffffffu, ci, off);
            int   os = __shfl_xor_sync(0xffffffffu, sl, off);
            if (ov > v || (ov == v && oi < ci)) { v = ov; ci = oi; sl = os; }
        }
        lx = s_cx[buf][sl]; ly = s_cy[buf][sl]; lz = s_cz[buf][sl];
        if (t == 0) s_inds[it] = ci;
    }
    __syncthreads();

    for (int i = t; i < NPQ; i += 1024) {
        int id = s_inds[i];
        out[OUT_INDS + b*NPQ + i] = (float)id;
        const float* xb = xyz + ((size_t)b*NN + id)*3;
        out[((size_t)b*NPQ + i)*3 + 0] = xb[0];
        out[((size_t)b*NPQ + i)*3 + 1] = xb[1];
        out[((size_t)b*NPQ + i)*3 + 2] = xb[2];
    }
}

// ---------------------------------------------------------------------------
// Ball query: one warp per query. First-16-in-index-order semantics via ballot.
__global__ __launch_bounds__(256) void bq_kernel(
    const float* __restrict__ xyz, const float* __restrict__ out)
{
    int q = blockIdx.x*8 + (threadIdx.x >> 5);
    int lane = threadIdx.x & 31;
    int b = q >> 9;
    const float R2c = (float)(0.3*0.3);
    const float RAD = 0.3f;

    float qx = out[(size_t)q*3+0];
    float qy = out[(size_t)q*3+1];
    float qz = out[(size_t)q*3+2];
    const float* xb = xyz + (size_t)b*NN*3;

    int found = 0, firstIdx = -1;
    for (int s = 0; s < NN/32 && found < NSAMP; ++s) {
        int i = s*32 + lane;
        float x = xb[i*3+0], y = xb[i*3+1], z = xb[i*3+2];
        float dx = __fadd_rn(qx, -x);
        float dy = __fadd_rn(qy, -y);
        float dz = __fadd_rn(qz, -z);
        float d  = __fadd_rn(__fadd_rn(__fmul_rn(dx,dx), __fmul_rn(dy,dy)),
                             __fmul_rn(dz,dz));
        bool pred = d < R2c;
        unsigned mask = __ballot_sync(0xffffffffu, pred);
        if (firstIdx < 0 && mask) firstIdx = s*32 + __ffs(mask) - 1;
        if (pred) {
            int rank = __popc(mask & ((1u << lane) - 1u));
            int pos = found + rank;
            if (pos < NSAMP) {
                g_idx[q*NSAMP + pos] = i;
                g_gxyz[((size_t)q*NSAMP + pos)*3 + 0] = __fdiv_rn(__fadd_rn(x, -qx), RAD);
                g_gxyz[((size_t)q*NSAMP + pos)*3 + 1] = __fdiv_rn(__fadd_rn(y, -qy), RAD);
                g_gxyz[((size_t)q*NSAMP + pos)*3 + 2] = __fdiv_rn(__fadd_rn(z, -qz), RAD);
            }
        }
        found += __popc(mask);
    }
    if (found < NSAMP) {
        float fx = xb[firstIdx*3+0], fy = xb[firstIdx*3+1], fz = xb[firstIdx*3+2];
        float p0 = __fdiv_rn(__fadd_rn(fx, -qx), RAD);
        float p1 = __fdiv_rn(__fadd_rn(fy, -qy), RAD);
        float p2 = __fdiv_rn(__fadd_rn(fz, -qz), RAD);
        if (lane >= found && lane < NSAMP) {
            g_idx[q*NSAMP + lane] = firstIdx;
            g_gxyz[((size_t)q*NSAMP + lane)*3 + 0] = p0;
            g_gxyz[((size_t)q*NSAMP + lane)*3 + 1] = p1;
            g_gxyz[((size_t)q*NSAMP + lane)*3 + 2] = p2;
        }
    }
}

// ---------------------------------------------------------------------------
// GEMM1 (tf32 tensor cores): PF[b,m,o] = sum_c feat[b,c,m] * W1f[o,c]
// per batch M=4096, N=128, K=256. Block: 128x128x32, 8 warps (2x4), warp 64x32.
__global__ __launch_bounds__(256) void gemm1_tc(const float* __restrict__ feat)
{
    __shared__ float As[32*132];   // [k][m], stride 132
    __shared__ float Bs[128*36];   // [n][k], stride 36
    int b = blockIdx.z;
    int mBase = blockIdx.x*128;
    const float* A = feat + (size_t)b*CC*NN;
    float* C = g_PF + ((size_t)b*NN + mBase)*HIDC;
    int tid = threadIdx.x;
    int lane = tid & 31, wid = tid >> 5;
    int wm = wid >> 2, wn = wid & 3;     // 2 x 4 warp grid
    int lq = lane >> 2, lr = lane & 3;

    float c[4][4][4];
#pragma unroll
    for (int i = 0; i < 4; i++)
#pragma unroll
        for (int j = 0; j < 4; j++)
#pragma unroll
            for (int r = 0; r < 4; r++) c[i][j][r] = 0.f;

    for (int kb = 0; kb < CC/32; kb++) {
        // A tile: coalesced along m, direct [k][m] store
#pragma unroll
        for (int r = 0; r < 4; r++) {
            int p = tid + 256*r;
            int k = p >> 5, mq = p & 31;
            float4 v = *(const float4*)(A + (size_t)(kb*32 + k)*NN + mBase + mq*4);
            *(float4*)(As + k*132 + mq*4) = v;
        }
        // B tile: W1f packed [n][256]
#pragma unroll
        for (int r = 0; r < 4; r++) {
            int p = tid + 256*r;
            int n = p >> 3, kq = p & 7;
            float4 v = *(const float4*)(g_W1f + n*CC + kb*32 + kq*4);
            *(float4*)(Bs + n*36 + kq*4) = v;
        }
        __syncthreads();
#pragma unroll
        for (int ks = 0; ks < 4; ks++) {
            int k0 = ks*8;
            uint32_t af[4][4], bf[4][2];
#pragma unroll
            for (int mi = 0; mi < 4; mi++) {
                int m0 = wm*64 + mi*16;
                af[mi][0] = __float_as_uint(As[(k0+lr  )*132 + m0 + lq    ]);
                af[mi][1] = __float_as_uint(As[(k0+lr  )*132 + m0 + 8 + lq]);
                af[mi][2] = __float_as_uint(As[(k0+lr+4)*132 + m0 + lq    ]);
                af[mi][3] = __float_as_uint(As[(k0+lr+4)*132 + m0 + 8 + lq]);
            }
#pragma unroll
            for (int nj = 0; nj < 4; nj++) {
                int n0 = wn*32 + nj*8;
                bf[nj][0] = __float_as_uint(Bs[(n0+lq)*36 + k0 + lr    ]);
                bf[nj][1] = __float_as_uint(Bs[(n0+lq)*36 + k0 + lr + 4]);
            }
#pragma unroll
            for (int mi = 0; mi < 4; mi++)
#pragma unroll
                for (int nj = 0; nj < 4; nj++)
                    MMA8(c[mi][nj], af[mi], bf[nj]);
        }
        __syncthreads();
    }
#pragma unroll
    for (int mi = 0; mi < 4; mi++) {
#pragma unroll
        for (int nj = 0; nj < 4; nj++) {
            int gr  = wm*64 + mi*16 + lq;
            int col = wn*32 + nj*8 + 2*lr;
            float2 v0 = make_float2(c[mi][nj][0], c[mi][nj][1]);
            float2 v1 = make_float2(c[mi][nj][2], c[mi][nj][3]);
            *(float2*)(C + (size_t)gr*HIDC + col)     = v0;
            *(float2*)(C + (size_t)(gr+8)*HIDC + col) = v1;
        }
    }
}

// ---------------------------------------------------------------------------
// Assemble conv1: Y1 = PF[gathered] + W1xyz . gxyz  + layer-0 BN stats.
__global__ __launch_bounds__(256) void assemble_kernel(const float* __restrict__ w1)
{
    __shared__ float s_wx[HIDC], s_wy[HIDC], s_wz[HIDC];
    __shared__ float s_sum[HIDC], s_sq[HIDC];
    int tid = threadIdx.x, lane = tid & 31, w = tid >> 5;
    if (tid < HIDC) {
        s_wx[tid] = w1[tid*(CC+3) + 0];
        s_wy[tid] = w1[tid*(CC+3) + 1];
        s_wz[tid] = w1[tid*(CC+3) + 2];
        s_sum[tid] = 0.f; s_sq[tid] = 0.f;
    }
    __syncthreads();

    float ls[4] = {0,0,0,0}, lqa[4] = {0,0,0,0};
    float wx[4], wy[4], wz[4];
#pragma unroll
    for (int j = 0; j < 4; j++) {
        int o = lane*4 + j;
        wx[j] = s_wx[o]; wy[j] = s_wy[o]; wz[j] = s_wz[o];
    }
    for (int i = 0; i < 16; i++) {
        int p = blockIdx.x*128 + w*16 + i;
        int b = p >> 13;
        int n = g_idx[p];
        float gx = g_gxyz[(size_t)p*3+0];
        float gy = g_gxyz[(size_t)p*3+1];
        float gz = g_gxyz[(size_t)p*3+2];
        float4 v = *(const float4*)(g_PF + ((size_t)b*NN + n)*HIDC + lane*4);
        float y[4] = {v.x, v.y, v.z, v.w};
#pragma unroll
        for (int j = 0; j < 4; j++) {
            float r = y[j] + wx[j]*gx + wy[j]*gy + wz[j]*gz;
            y[j] = r;
            ls[j] += r; lqa[j] += r*r;
        }
        *(float4*)(g_Y1 + (size_t)p*HIDC + lane*4) = make_float4(y[0],y[1],y[2],y[3]);
    }
#pragma unroll
    for (int j = 0; j < 4; j++) {
        atomicAdd(&s_sum[lane*4 + j], ls[j]);
        atomicAdd(&s_sq [lane*4 + j], lqa[j]);
    }
    __syncthreads();
    if (tid < HIDC)      atomicAdd(&g_stats[0*256 + tid], (double)s_sum[tid]);
    else if (tid < 256)  atomicAdd(&g_stats[0*256 + 128 + (tid-128)], (double)s_sq[tid-128]);
}

// ---------------------------------------------------------------------------
__global__ void finalize_bn_kernel(int L, const float* __restrict__ g,
                                   const float* __restrict__ be)
{
    int cc = threadIdx.x;
    if (cc >= HIDC) return;
    const double cnt = (double)NPIX;
    double s = g_stats[L*256 + cc];
    double q = g_stats[L*256 + 128 + cc];
    double m = s / cnt;
    double v = q / cnt - m*m;
    if (v < 0.0) v = 0.0;
    float scale = g[cc] / sqrtf((float)v + 1e-5f);
    g_bn[L*384 + cc]       = (float)m;
    g_bn[L*384 + 128 + cc] = scale;
    g_bn[L*384 + 256 + cc] = be[cc];
}

// ---------------------------------------------------------------------------
// NT GEMM (tf32): C[m,o] = sum_k relu(bn_prev(A[m,k])) * W[o,k]
// M=262144, N=128, K=128. Fused next-layer BN stats in epilogue.
__global__ __launch_bounds__(256) void gemm_nt_tc(const float* __restrict__ W, int layer)
{
    __shared__ float As[128*36];   // [m][k] stride 36
    __shared__ float Bs[128*36];   // [n][k] stride 36
    __shared__ float s_bnp[384];
    __shared__ float s_sum[HIDC], s_sq[HIDC];
    const float* A  = (layer == 1) ? g_Y1 : g_Y2;
    float*       Y  = (layer == 1) ? g_Y2 : g_Y1;
    const float* bnp = g_bn + (layer-1)*384;

    int tid = threadIdx.x;
    int lane = tid & 31, wid = tid >> 5;
    int wm = wid >> 2, wn = wid & 3;
    int lq = lane >> 2, lr = lane & 3;
    if (tid < HIDC) { s_sum[tid] = 0.f; s_sq[tid] = 0.f; }
    for (int i = tid; i < 384; i += 256) s_bnp[i] = bnp[i];
    __syncthreads();

    size_t mBase = (size_t)blockIdx.x * 128;
    float c[4][4][4];
#pragma unroll
    for (int i = 0; i < 4; i++)
#pragma unroll
        for (int j = 0; j < 4; j++)
#pragma unroll
            for (int r = 0; r < 4; r++) c[i][j][r] = 0.f;

    for (int kb = 0; kb < 4; kb++) {
#pragma unroll
        for (int r = 0; r < 4; r++) {
            int p = tid + 256*r;
            int row = p >> 3, kq = p & 7;
            int ch = kb*32 + kq*4;
            float4 v = *(const float4*)(A + (mBase + row)*HIDC + ch);
            float4 o4;
            o4.x = fmaxf(0.f, (v.x - s_bnp[ch+0])*s_bnp[128+ch+0] + s_bnp[256+ch+0]);
            o4.y = fmaxf(0.f, (v.y - s_bnp[ch+1])*s_bnp[128+ch+1] + s_bnp[256+ch+1]);
            o4.z = fmaxf(0.f, (v.z - s_bnp[ch+2])*s_bnp[128+ch+2] + s_bnp[256+ch+2]);
            o4.w = fmaxf(0.f, (v.w - s_bnp[ch+3])*s_bnp[128+ch+3] + s_bnp[256+ch+3]);
            *(float4*)(As + row*36 + kq*4) = o4;
            float4 wv = *(const float4*)(W + (size_t)row*HIDC + ch);
            *(float4*)(Bs + row*36 + kq*4) = wv;
        }
        __syncthreads();
#pragma unroll
        for (int ks = 0; ks < 4; ks++) {
            int k0 = ks*8;
            uint32_t af[4][4], bf[4][2];
#pragma unroll
            for (int mi = 0; mi < 4; mi++) {
                int m0 = wm*64 + mi*16;
                af[mi][0] = __float_as_uint(As[(m0 + lq    )*36 + k0 + lr    ]);
                af[mi][1] = __float_as_uint(As[(m0 + 8 + lq)*36 + k0 + lr    ]);
                af[mi][2] = __float_as_uint(As[(m0 + lq    )*36 + k0 + lr + 4]);
                af[mi][3] = __float_as_uint(As[(m0 + 8 + lq)*36 + k0 + lr + 4]);
            }
#pragma unroll
            for (int nj = 0; nj < 4; nj++) {
                int n0 = wn*32 + nj*8;
                bf[nj][0] = __float_as_uint(Bs[(n0+lq)*36 + k0 + lr    ]);
                bf[nj][1] = __float_as_uint(Bs[(n0+lq)*36 + k0 + lr + 4]);
            }
#pragma unroll
            for (int mi = 0; mi < 4; mi++)
#pragma unroll
                for (int nj = 0; nj < 4; nj++)
                    MMA8(c[mi][nj], af[mi], bf[nj]);
        }
        __syncthreads();
    }
    // write + per-channel stats
#pragma unroll
    for (int mi = 0; mi < 4; mi++) {
#pragma unroll
        for (int nj = 0; nj < 4; nj++) {
            size_t gr = mBase + wm*64 + mi*16 + lq;
            int col = wn*32 + nj*8 + 2*lr;
            *(float2*)(Y + gr*HIDC + col)     = make_float2(c[mi][nj][0], c[mi][nj][1]);
            *(float2*)(Y + (gr+8)*HIDC + col) = make_float2(c[mi][nj][2], c[mi][nj][3]);
        }
    }
#pragma unroll
    for (int nj = 0; nj < 4; nj++) {
        int ch = wn*32 + nj*8 + 2*lr;
        float s0 = 0.f, q0 = 0.f, s1 = 0.f, q1 = 0.f;
#pragma unroll
        for (int mi = 0; mi < 4; mi++) {
            float x;
            x = c[mi][nj][0]; s0 += x; q0 += x*x;
            x = c[mi][nj][2]; s0 += x; q0 += x*x;
            x = c[mi][nj][1]; s1 += x; q1 += x*x;
            x = c[mi][nj][3]; s1 += x; q1 += x*x;
        }
        atomicAdd(&s_sum[ch],   s0); atomicAdd(&s_sq[ch],   q0);
        atomicAdd(&s_sum[ch+1], s1); atomicAdd(&s_sq[ch+1], q1);
    }
    __syncthreads();
    if (tid < HIDC)      atomicAdd(&g_stats[layer*256 + tid], (double)s_sum[tid]);
    else if (tid < 256)  atomicAdd(&g_stats[layer*256 + 128 + (tid-128)], (double)s_sq[tid-128]);
}

// ---------------------------------------------------------------------------
// Maxpool over NS with BN3+ReLU folded in; smem transpose for coalesced writes.
__global__ __launch_bounds__(256) void maxpool_kernel(float* __restrict__ out)
{
    __shared__ float T[HIDC][33];
    int b  = blockIdx.x >> 4;
    int pb = blockIdx.x & 15;
    int tid = threadIdx.x, lane = tid & 31, w = tid >> 5;
    const float* bnp = g_bn + 2*384;
    float mean[4], sc[4], bt[4];
#pragma unroll
    for (int j = 0; j < 4; j++) {
        int o = lane*4 + j;
        mean[j] = bnp[o]; sc[j] = bnp[128+o]; bt[j] = bnp[256+o];
    }
    for (int pi = 0; pi < 4; pi++) {
        int p = pb*32 + w*4 + pi;
        size_t base = ((size_t)(b*NPQ + p) * NSAMP) * HIDC;
        float mx[4] = {-3.4e38f, -3.4e38f, -3.4e38f, -3.4e38f};
#pragma unroll
        for (int s = 0; s < NSAMP; s++) {
            float4 v = *(const float4*)(g_Y1 + base + (size_t)s*HIDC + lane*4);
            mx[0] = fmaxf(mx[0], v.x);
            mx[1] = fmaxf(mx[1], v.y);
            mx[2] = fmaxf(mx[2], v.z);
            mx[3] = fmaxf(mx[3], v.w);
        }
#pragma unroll
        for (int j = 0; j < 4; j++)
            T[lane*4 + j][w*4 + pi] = fmaxf(0.f, (mx[j] - mean[j])*sc[j] + bt[j]);
    }
    __syncthreads();
#pragma unroll
    for (int r = 0; r < 16; r++) {
        int flat = tid + 256*r;
        int o = flat >> 5, pl = flat & 31;
        out[OUT_FEAT + (size_t)b*(HIDC*NPQ) + (size_t)o*NPQ + pb*32 + pl] = T[o][pl];
    }
}

// ---------------------------------------------------------------------------
extern "C" void kernel_launch(void* const* d_in, const int* in_sizes, int n_in,
                              void* d_out, int out_size)
{
    const float* xyz  = (const float*)d_in[0];
    const float* feat = (const float*)d_in[1];
    const float* seed = (const float*)d_in[2];
    const float* w1   = (const float*)d_in[3];
    const float* g1   = (const float*)d_in[4];
    const float* be1  = (const float*)d_in[5];
    const float* w2   = (const float*)d_in[6];
    const float* g2   = (const float*)d_in[7];
    const float* be2  = (const float*)d_in[8];
    const float* w3   = (const float*)d_in[9];
    const float* g3   = (const float*)d_in[10];
    const float* be3  = (const float*)d_in[11];
    float* out = (float*)d_out;

    zero_stats_kernel<<<3, 256>>>();
    prep_w1_kernel<<<HIDC, CC>>>(w1);
    fps_kernel<<<BB, 1024>>>(seed, xyz, out);
    bq_kernel<<<(BB*NPQ)/8, 256>>>(xyz, out);
    gemm1_tc<<<dim3(NN/128, 1, BB), 256>>>(feat);
    assemble_kernel<<<NPIX/128, 256>>>(w1);
    finalize_bn_kernel<<<1, 128>>>(0, g1, be1);
    gemm_nt_tc<<<NPIX/128, 256>>>(w2, 1);
    finalize_bn_kernel<<<1, 128>>>(1, g2, be2);
    gemm_nt_tc<<<NPIX/128, 256>>>(w3, 2);
    finalize_bn_kernel<<<1, 128>>>(2, g3, be3);
    maxpool_kernel<<<BB*16, 256>>>(out);
}

// round 5
// speedup vs baseline: 1.0709x; 1.0709x over previous
#include <cuda_runtime.h>
#include <math.h>
#include <stdint.h>

#define BB    32
#define NN    4096
#define NPQ   512
#define NSAMP 16
#define CC    256
#define HIDC  128
#define NPIX  (BB*NPQ*NSAMP)
#define NPTS  (BB*NN)

#define OUT_FEAT (BB*NPQ*3)
#define OUT_INDS (OUT_FEAT + BB*HIDC*NPQ)

__device__ float  g_PF[(size_t)NPTS*HIDC];
__device__ float  g_Y1[(size_t)NPIX*HIDC];
__device__ float  g_Y2[(size_t)NPIX*HIDC];
__device__ float  g_MX[(size_t)BB*NPQ*HIDC];
__device__ int    g_idx[NPIX];
__device__ float  g_gxyz[(size_t)NPIX*3];
__device__ double g_stats[3*2*HIDC];
__device__ float  g_bn[3*3*HIDC];
__device__ float  g_W1f[HIDC*CC];

#define MMA8(c, a, b) asm volatile( \
  "mma.sync.aligned.m16n8k8.row.col.f32.tf32.tf32.f32 " \
  "{%0,%1,%2,%3}, {%4,%5,%6,%7}, {%8,%9}, {%0,%1,%2,%3};" \
  : "+f"((c)[0]), "+f"((c)[1]), "+f"((c)[2]), "+f"((c)[3]) \
  : "r"((a)[0]), "r"((a)[1]), "r"((a)[2]), "r"((a)[3]), "r"((b)[0]), "r"((b)[1]))

__global__ void zero_stats_kernel() {
    int i = blockIdx.x*256 + threadIdx.x;
    if (i < 3*2*HIDC) g_stats[i] = 0.0;
}

__global__ void prep_w1_kernel(const float* __restrict__ w1) {
    int o = blockIdx.x, k = threadIdx.x;
    g_W1f[o*CC + k] = w1[o*(CC+3) + 3 + k];
}

// ---------------- FPS (unchanged from passing R3) ----------------
__global__ __launch_bounds__(1024) void fps_kernel(
    const float* __restrict__ seed, const float* __restrict__ xyz,
    float* __restrict__ out)
{
    int b = blockIdx.x, t = threadIdx.x;
    int lane = t & 31, wid = t >> 5;
    __shared__ float s_cv[2][32], s_cx[2][32], s_cy[2][32], s_cz[2][32];
    __shared__ int   s_ci[2][32];
    __shared__ int   s_inds[NPQ];

    const float* sb = seed + (size_t)b*NN*3;
    float px[4], py[4], pz[4], dist[4];
#pragma unroll
    for (int j = 0; j < 4; j++) {
        int i = t + j*1024;
        px[j] = sb[i*3+0]; py[j] = sb[i*3+1]; pz[j] = sb[i*3+2];
        dist[j] = 1e10f;
    }
    if (t == 0) s_inds[0] = 0;
    float lx = sb[0], ly = sb[1], lz = sb[2];

    for (int it = 1; it < NPQ; ++it) {
        float bv = -1.0f; int bi = 0;
        float bx = 0.f, by = 0.f, bz = 0.f;
#pragma unroll
        for (int j = 0; j < 4; j++) {
            float dx = __fadd_rn(px[j], -lx);
            float dy = __fadd_rn(py[j], -ly);
            float dz = __fadd_rn(pz[j], -lz);
            float d  = __fadd_rn(__fadd_rn(__fmul_rn(dx,dx), __fmul_rn(dy,dy)),
                                 __fmul_rn(dz,dz));
            dist[j] = fminf(dist[j], d);
            if (dist[j] > bv) { bv = dist[j]; bi = t + j*1024;
                                bx = px[j]; by = py[j]; bz = pz[j]; }
        }
#pragma unroll
        for (int off = 16; off > 0; off >>= 1) {
            float ov = __shfl_xor_sync(0xffffffffu, bv, off);
            int   oi = __shfl_xor_sync(0xffffffffu, bi, off);
            float ox = __shfl_xor_sync(0xffffffffu, bx, off);
            float oy = __shfl_xor_sync(0xffffffffu, by, off);
            float oz = __shfl_xor_sync(0xffffffffu, bz, off);
            if (ov > bv || (ov == bv && oi < bi)) {
                bv = ov; bi = oi; bx = ox; by = oy; bz = oz;
            }
        }
        int buf = it & 1;
        if (lane == 0) {
            s_cv[buf][wid] = bv; s_ci[buf][wid] = bi;
            s_cx[buf][wid] = bx; s_cy[buf][wid] = by; s_cz[buf][wid] = bz;
        }
        __syncthreads();
        float v  = s_cv[buf][lane];
        int   ci = s_ci[buf][lane];
        int   sl = lane;
#pragma unroll
        for (int off = 16; off > 0; off >>= 1) {
            float ov = __shfl_xor_sync(0xffffffffu, v,  off);
            int   oi = __shfl_xor_sync(0xffffffffu, ci, off);
            int   os = __shfl_xor_sync(0xffffffffu, sl, off);
            if (ov > v || (ov == v && oi < ci)) { v = ov; ci = oi; sl = os; }
        }
        lx = s_cx[buf][sl]; ly = s_cy[buf][sl]; lz = s_cz[buf][sl];
        if (t == 0) s_inds[it] = ci;
    }
    __syncthreads();
    for (int i = t; i < NPQ; i += 1024) {
        int id = s_inds[i];
        out[OUT_INDS + b*NPQ + i] = (float)id;
        const float* xb = xyz + ((size_t)b*NN + id)*3;
        out[((size_t)b*NPQ + i)*3 + 0] = xb[0];
        out[((size_t)b*NPQ + i)*3 + 1] = xb[1];
        out[((size_t)b*NPQ + i)*3 + 2] = xb[2];
    }
}

// ---------------- Ball query v2: smem-staged cloud, 4 queries/warp ----------
__global__ __launch_bounds__(256) void bq2_kernel(
    const float* __restrict__ xyz, const float* __restrict__ out)
{
    __shared__ float sx[NN], sy[NN], sz[NN];
    int tid = threadIdx.x, lane = tid & 31, w = tid >> 5;
    int qbase = blockIdx.x * 32;            // 32 queries/block, same batch
    int b = qbase >> 9;
    const float* xb = xyz + (size_t)b*NN*3;
    for (int i = tid; i < NN; i += 256) {
        sx[i] = xb[i*3+0]; sy[i] = xb[i*3+1]; sz[i] = xb[i*3+2];
    }
    __syncthreads();

    const float R2c = (float)(0.3*0.3);
    const float RAD = 0.3f;
    int q0 = qbase + w*4;
    float qx[4], qy[4], qz[4];
    int found[4], first[4];
#pragma unroll
    for (int j = 0; j < 4; j++) {
        qx[j] = out[(size_t)(q0+j)*3+0];
        qy[j] = out[(size_t)(q0+j)*3+1];
        qz[j] = out[(size_t)(q0+j)*3+2];
        found[j] = 0; first[j] = -1;
    }
    for (int s = 0; s < NN/32; s++) {
        int i = s*32 + lane;
        float x = sx[i], y = sy[i], z = sz[i];
#pragma unroll
        for (int j = 0; j < 4; j++) {
            if (found[j] >= NSAMP) continue;     // warp-uniform
            float dx = __fadd_rn(qx[j], -x);
            float dy = __fadd_rn(qy[j], -y);
            float dz = __fadd_rn(qz[j], -z);
            float d  = __fadd_rn(__fadd_rn(__fmul_rn(dx,dx), __fmul_rn(dy,dy)),
                                 __fmul_rn(dz,dz));
            bool pred = d < R2c;
            unsigned mask = __ballot_sync(0xffffffffu, pred);
            if (first[j] < 0 && mask) first[j] = s*32 + __ffs(mask) - 1;
            if (pred) {
                int pos = found[j] + __popc(mask & ((1u << lane) - 1u));
                if (pos < NSAMP) {
                    int qg = q0 + j;
                    g_idx[qg*NSAMP + pos] = i;
                    g_gxyz[((size_t)qg*NSAMP + pos)*3 + 0] = __fdiv_rn(__fadd_rn(x, -qx[j]), RAD);
                    g_gxyz[((size_t)qg*NSAMP + pos)*3 + 1] = __fdiv_rn(__fadd_rn(y, -qy[j]), RAD);
                    g_gxyz[((size_t)qg*NSAMP + pos)*3 + 2] = __fdiv_rn(__fadd_rn(z, -qz[j]), RAD);
                }
            }
            found[j] += __popc(mask);
        }
        if (found[0] >= NSAMP && found[1] >= NSAMP &&
            found[2] >= NSAMP && found[3] >= NSAMP) break;
    }
#pragma unroll
    for (int j = 0; j < 4; j++) {
        if (found[j] < NSAMP) {
            int fi = first[j];
            float x = sx[fi], y = sy[fi], z = sz[fi];
            float p0 = __fdiv_rn(__fadd_rn(x, -qx[j]), RAD);
            float p1 = __fdiv_rn(__fadd_rn(y, -qy[j]), RAD);
            float p2 = __fdiv_rn(__fadd_rn(z, -qz[j]), RAD);
            if (lane >= found[j] && lane < NSAMP) {
                int qg = q0 + j;
                g_idx[qg*NSAMP + lane] = fi;
                g_gxyz[((size_t)qg*NSAMP + lane)*3 + 0] = p0;
                g_gxyz[((size_t)qg*NSAMP + lane)*3 + 1] = p1;
                g_gxyz[((size_t)qg*NSAMP + lane)*3 + 2] = p2;
            }
        }
    }
}

// ---------------- GEMM1 tf32 (unchanged) ----------------
__global__ __launch_bounds__(256) void gemm1_tc(const float* __restrict__ feat)
{
    __shared__ float As[32*132];
    __shared__ float Bs[128*36];
    int b = blockIdx.z;
    int mBase = blockIdx.x*128;
    const float* A = feat + (size_t)b*CC*NN;
    float* C = g_PF + ((size_t)b*NN + mBase)*HIDC;
    int tid = threadIdx.x;
    int lane = tid & 31, wid = tid >> 5;
    int wm = wid >> 2, wn = wid & 3;
    int lq = lane >> 2, lr = lane & 3;

    float c[4][4][4];
#pragma unroll
    for (int i = 0; i < 4; i++)
#pragma unroll
        for (int j = 0; j < 4; j++)
#pragma unroll
            for (int r = 0; r < 4; r++) c[i][j][r] = 0.f;

    for (int kb = 0; kb < CC/32; kb++) {
#pragma unroll
        for (int r = 0; r < 4; r++) {
            int p = tid + 256*r;
            int k = p >> 5, mq = p & 31;
            float4 v = *(const float4*)(A + (size_t)(kb*32 + k)*NN + mBase + mq*4);
            *(float4*)(As + k*132 + mq*4) = v;
        }
#pragma unroll
        for (int r = 0; r < 4; r++) {
            int p = tid + 256*r;
            int n = p >> 3, kq = p & 7;
            float4 v = *(const float4*)(g_W1f + n*CC + kb*32 + kq*4);
            *(float4*)(Bs + n*36 + kq*4) = v;
        }
        __syncthreads();
#pragma unroll
        for (int ks = 0; ks < 4; ks++) {
            int k0 = ks*8;
            uint32_t af[4][4], bf[4][2];
#pragma unroll
            for (int mi = 0; mi < 4; mi++) {
                int m0 = wm*64 + mi*16;
                af[mi][0] = __float_as_uint(As[(k0+lr  )*132 + m0 + lq    ]);
                af[mi][1] = __float_as_uint(As[(k0+lr  )*132 + m0 + 8 + lq]);
                af[mi][2] = __float_as_uint(As[(k0+lr+4)*132 + m0 + lq    ]);
                af[mi][3] = __float_as_uint(As[(k0+lr+4)*132 + m0 + 8 + lq]);
            }
#pragma unroll
            for (int nj = 0; nj < 4; nj++) {
                int n0 = wn*32 + nj*8;
                bf[nj][0] = __float_as_uint(Bs[(n0+lq)*36 + k0 + lr    ]);
                bf[nj][1] = __float_as_uint(Bs[(n0+lq)*36 + k0 + lr + 4]);
            }
#pragma unroll
            for (int mi = 0; mi < 4; mi++)
#pragma unroll
                for (int nj = 0; nj < 4; nj++)
                    MMA8(c[mi][nj], af[mi], bf[nj]);
        }
        __syncthreads();
    }
#pragma unroll
    for (int mi = 0; mi < 4; mi++) {
#pragma unroll
        for (int nj = 0; nj < 4; nj++) {
            int gr  = wm*64 + mi*16 + lq;
            int col = wn*32 + nj*8 + 2*lr;
            *(float2*)(C + (size_t)gr*HIDC + col)     = make_float2(c[mi][nj][0], c[mi][nj][1]);
            *(float2*)(C + (size_t)(gr+8)*HIDC + col) = make_float2(c[mi][nj][2], c[mi][nj][3]);
        }
    }
}

// ---------------- assemble (unchanged) ----------------
__global__ __launch_bounds__(256) void assemble_kernel(const float* __restrict__ w1)
{
    __shared__ float s_wx[HIDC], s_wy[HIDC], s_wz[HIDC];
    __shared__ float s_sum[HIDC], s_sq[HIDC];
    int tid = threadIdx.x, lane = tid & 31, w = tid >> 5;
    if (tid < HIDC) {
        s_wx[tid] = w1[tid*(CC+3) + 0];
        s_wy[tid] = w1[tid*(CC+3) + 1];
        s_wz[tid] = w1[tid*(CC+3) + 2];
        s_sum[tid] = 0.f; s_sq[tid] = 0.f;
    }
    __syncthreads();

    float ls[4] = {0,0,0,0}, lqa[4] = {0,0,0,0};
    float wx[4], wy[4], wz[4];
#pragma unroll
    for (int j = 0; j < 4; j++) {
        int o = lane*4 + j;
        wx[j] = s_wx[o]; wy[j] = s_wy[o]; wz[j] = s_wz[o];
    }
    for (int i = 0; i < 16; i++) {
        int p = blockIdx.x*128 + w*16 + i;
        int b = p >> 13;
        int n = g_idx[p];
        float gx = g_gxyz[(size_t)p*3+0];
        float gy = g_gxyz[(size_t)p*3+1];
        float gz = g_gxyz[(size_t)p*3+2];
        float4 v = *(const float4*)(g_PF + ((size_t)b*NN + n)*HIDC + lane*4);
        float y[4] = {v.x, v.y, v.z, v.w};
#pragma unroll
        for (int j = 0; j < 4; j++) {
            float r = y[j] + wx[j]*gx + wy[j]*gy + wz[j]*gz;
            y[j] = r;
            ls[j] += r; lqa[j] += r*r;
        }
        *(float4*)(g_Y1 + (size_t)p*HIDC + lane*4) = make_float4(y[0],y[1],y[2],y[3]);
    }
#pragma unroll
    for (int j = 0; j < 4; j++) {
        atomicAdd(&s_sum[lane*4 + j], ls[j]);
        atomicAdd(&s_sq [lane*4 + j], lqa[j]);
    }
    __syncthreads();
    if (tid < HIDC)      atomicAdd(&g_stats[0*256 + tid], (double)s_sum[tid]);
    else if (tid < 256)  atomicAdd(&g_stats[0*256 + 128 + (tid-128)], (double)s_sq[tid-128]);
}

__global__ void finalize_bn_kernel(int L, const float* __restrict__ g,
                                   const float* __restrict__ be)
{
    int cc = threadIdx.x;
    if (cc >= HIDC) return;
    const double cnt = (double)NPIX;
    double s = g_stats[L*256 + cc];
    double q = g_stats[L*256 + 128 + cc];
    double m = s / cnt;
    double v = q / cnt - m*m;
    if (v < 0.0) v = 0.0;
    float scale = g[cc] / sqrtf((float)v + 1e-5f);
    g_bn[L*384 + cc]       = (float)m;
    g_bn[L*384 + 128 + cc] = scale;
    g_bn[L*384 + 256 + cc] = be[cc];
}

// ---------------- NT GEMM tf32; layer 2 fuses maxpool (writes g_MX only) ----
__global__ __launch_bounds__(256) void gemm_nt_tc(const float* __restrict__ W, int layer)
{
    __shared__ float As[128*36];
    __shared__ float Bs[128*36];
    __shared__ float s_bnp[384];
    __shared__ float s_sum[HIDC], s_sq[HIDC];
    const float* A  = (layer == 1) ? g_Y1 : g_Y2;
    const float* bnp = g_bn + (layer-1)*384;

    int tid = threadIdx.x;
    int lane = tid & 31, wid = tid >> 5;
    int wm = wid >> 2, wn = wid & 3;
    int lq = lane >> 2, lr = lane & 3;
    if (tid < HIDC) { s_sum[tid] = 0.f; s_sq[tid] = 0.f; }
    for (int i = tid; i < 384; i += 256) s_bnp[i] = bnp[i];
    __syncthreads();

    size_t mBase = (size_t)blockIdx.x * 128;
    float c[4][4][4];
#pragma unroll
    for (int i = 0; i < 4; i++)
#pragma unroll
        for (int j = 0; j < 4; j++)
#pragma unroll
            for (int r = 0; r < 4; r++) c[i][j][r] = 0.f;

    for (int kb = 0; kb < 4; kb++) {
#pragma unroll
        for (int r = 0; r < 4; r++) {
            int p = tid + 256*r;
            int row = p >> 3, kq = p & 7;
            int ch = kb*32 + kq*4;
            float4 v = *(const float4*)(A + (mBase + row)*HIDC + ch);
            float4 o4;
            o4.x = fmaxf(0.f, (v.x - s_bnp[ch+0])*s_bnp[128+ch+0] + s_bnp[256+ch+0]);
            o4.y = fmaxf(0.f, (v.y - s_bnp[ch+1])*s_bnp[128+ch+1] + s_bnp[256+ch+1]);
            o4.z = fmaxf(0.f, (v.z - s_bnp[ch+2])*s_bnp[128+ch+2] + s_bnp[256+ch+2]);
            o4.w = fmaxf(0.f, (v.w - s_bnp[ch+3])*s_bnp[128+ch+3] + s_bnp[256+ch+3]);
            *(float4*)(As + row*36 + kq*4) = o4;
            float4 wv = *(const float4*)(W + (size_t)row*HIDC + ch);
            *(float4*)(Bs + row*36 + kq*4) = wv;
        }
        __syncthreads();
#pragma unroll
        for (int ks = 0; ks < 4; ks++) {
            int k0 = ks*8;
            uint32_t af[4][4], bf[4][2];
#pragma unroll
            for (int mi = 0; mi < 4; mi++) {
                int m0 = wm*64 + mi*16;
                af[mi][0] = __float_as_uint(As[(m0 + lq    )*36 + k0 + lr    ]);
                af[mi][1] = __float_as_uint(As[(m0 + 8 + lq)*36 + k0 + lr    ]);
                af[mi][2] = __float_as_uint(As[(m0 + lq    )*36 + k0 + lr + 4]);
                af[mi][3] = __float_as_uint(As[(m0 + 8 + lq)*36 + k0 + lr + 4]);
            }
#pragma unroll
            for (int nj = 0; nj < 4; nj++) {
                int n0 = wn*32 + nj*8;
                bf[nj][0] = __float_as_uint(Bs[(n0+lq)*36 + k0 + lr    ]);
                bf[nj][1] = __float_as_uint(Bs[(n0+lq)*36 + k0 + lr + 4]);
            }
#pragma unroll
            for (int mi = 0; mi < 4; mi++)
#pragma unroll
                for (int nj = 0; nj < 4; nj++)
                    MMA8(c[mi][nj], af[mi], bf[nj]);
        }
        __syncthreads();
    }
    if (layer == 1) {
#pragma unroll
        for (int mi = 0; mi < 4; mi++)
#pragma unroll
            for (int nj = 0; nj < 4; nj++) {
                size_t gr = mBase + wm*64 + mi*16 + lq;
                int col = wn*32 + nj*8 + 2*lr;
                *(float2*)(g_Y2 + gr*HIDC + col)     = make_float2(c[mi][nj][0], c[mi][nj][1]);
                *(float2*)(g_Y2 + (gr+8)*HIDC + col) = make_float2(c[mi][nj][2], c[mi][nj][3]);
            }
    } else {
        // rows m0..m0+15 = one query; reduce max over lq (lane bits 2..4)
#pragma unroll
        for (int mi = 0; mi < 4; mi++) {
            int qg = blockIdx.x*8 + wm*4 + mi;
#pragma unroll
            for (int nj = 0; nj < 4; nj++) {
                float m0v = fmaxf(c[mi][nj][0], c[mi][nj][2]);
                float m1v = fmaxf(c[mi][nj][1], c[mi][nj][3]);
#pragma unroll
                for (int o = 4; o <= 16; o <<= 1) {
                    m0v = fmaxf(m0v, __shfl_xor_sync(0xffffffffu, m0v, o));
                    m1v = fmaxf(m1v, __shfl_xor_sync(0xffffffffu, m1v, o));
                }
                if (lq == 0) {
                    int col = wn*32 + nj*8 + 2*lr;
                    *(float2*)(g_MX + (size_t)qg*HIDC + col) = make_float2(m0v, m1v);
                }
            }
        }
    }
#pragma unroll
    for (int nj = 0; nj < 4; nj++) {
        int ch = wn*32 + nj*8 + 2*lr;
        float s0 = 0.f, q0 = 0.f, s1 = 0.f, q1 = 0.f;
#pragma unroll
        for (int mi = 0; mi < 4; mi++) {
            float x;
            x = c[mi][nj][0]; s0 += x; q0 += x*x;
            x = c[mi][nj][2]; s0 += x; q0 += x*x;
            x = c[mi][nj][1]; s1 += x; q1 += x*x;
            x = c[mi][nj][3]; s1 += x; q1 += x*x;
        }
        atomicAdd(&s_sum[ch],   s0); atomicAdd(&s_sq[ch],   q0);
        atomicAdd(&s_sum[ch+1], s1); atomicAdd(&s_sq[ch+1], q1);
    }
    __syncthreads();
    if (tid < HIDC)      atomicAdd(&g_stats[layer*256 + tid], (double)s_sum[tid]);
    else if (tid < 256)  atomicAdd(&g_stats[layer*256 + 128 + (tid-128)], (double)s_sq[tid-128]);
}

// ---------------- BN3+ReLU on g_MX + transpose to channel-major ----------
__global__ __launch_bounds__(256) void maxfinal_kernel(float* __restrict__ out)
{
    __shared__ float T[HIDC][33];
    int b = blockIdx.x >> 4, pb = blockIdx.x & 15;
    int tid = threadIdx.x;
    const float* bnp = g_bn + 2*384;
#pragma unroll
    for (int r = 0; r < 16; r++) {
        int idx = tid + 256*r;               // 32 queries * 128 channels
        int ql = idx >> 7, c = idx & 127;
        float v = g_MX[((size_t)(b*NPQ + pb*32 + ql))*HIDC + c];
        T[c][ql] = fmaxf(0.f, (v - bnp[c])*bnp[128+c] + bnp[256+c]);
    }
    __syncthreads();
#pragma unroll
    for (int r = 0; r < 16; r++) {
        int flat = tid + 256*r;
        int o = flat >> 5, pl = flat & 31;
        out[OUT_FEAT + (size_t)b*(HIDC*NPQ) + (size_t)o*NPQ + pb*32 + pl] = T[o][pl];
    }
}

// ---------------------------------------------------------------------------
extern "C" void kernel_launch(void* const* d_in, const int* in_sizes, int n_in,
                              void* d_out, int out_size)
{
    const float* xyz  = (const float*)d_in[0];
    const float* feat = (const float*)d_in[1];
    const float* seed = (const float*)d_in[2];
    const float* w1   = (const float*)d_in[3];
    const float* g1   = (const float*)d_in[4];
    const float* be1  = (const float*)d_in[5];
    const float* w2   = (const float*)d_in[6];
    const float* g2   = (const float*)d_in[7];
    const float* be2  = (const float*)d_in[8];
    const float* w3   = (const float*)d_in[9];
    const float* g3   = (const float*)d_in[10];
    const float* be3  = (const float*)d_in[11];
    float* out = (float*)d_out;

    zero_stats_kernel<<<3, 256>>>();
    prep_w1_kernel<<<HIDC, CC>>>(w1);
    fps_kernel<<<BB, 1024>>>(seed, xyz, out);
    bq2_kernel<<<(BB*NPQ)/32, 256>>>(xyz, out);
    gemm1_tc<<<dim3(NN/128, 1, BB), 256>>>(feat);
    assemble_kernel<<<NPIX/128, 256>>>(w1);
    finalize_bn_kernel<<<1, 128>>>(0, g1, be1);
    gemm_nt_tc<<<NPIX/128, 256>>>(w2, 1);
    finalize_bn_kernel<<<1, 128>>>(1, g2, be2);
    gemm_nt_tc<<<NPIX/128, 256>>>(w3, 2);
    finalize_bn_kernel<<<1, 128>>>(2, g3, be3);
    maxfinal_kernel<<<BB*16, 256>>>(out);
}

// round 7
// speedup vs baseline: 1.1411x; 1.0656x over previous
#include <cuda_runtime.h>
#include <cuda_fp16.h>
#include <math.h>
#include <stdint.h>

#define BB    32
#define NN    4096
#define NPQ   512
#define NSAMP 16
#define CC    256
#define HIDC  128
#define NPIX  (BB*NPQ*NSAMP)
#define NPTS  (BB*NN)

#define OUT_FEAT (BB*NPQ*3)
#define OUT_INDS (OUT_FEAT + BB*HIDC*NPQ)

__device__ float    g_PF[(size_t)NPTS*HIDC];
__device__ float    g_Y1[(size_t)NPIX*HIDC];
__device__ float    g_Y2[(size_t)NPIX*HIDC];
__device__ float    g_MX[(size_t)BB*NPQ*HIDC];
__device__ int      g_idx[NPIX];
__device__ float    g_gxyz[(size_t)NPIX*3];
__device__ double   g_stats[3*2*HIDC];
__device__ float    g_bn[3*3*HIDC];
__device__ __half   g_W1h[HIDC*CC];
__device__ __half   g_W2h[HIDC*HIDC];
__device__ __half   g_W3h[HIDC*HIDC];

// fp16 m16n8k16, f32 accum
#define MMAH(c, a, b) asm volatile( \
  "mma.sync.aligned.m16n8k16.row.col.f32.f16.f16.f32 " \
  "{%0,%1,%2,%3}, {%4,%5,%6,%7}, {%8,%9}, {%0,%1,%2,%3};" \
  : "+f"((c)[0]), "+f"((c)[1]), "+f"((c)[2]), "+f"((c)[3]) \
  : "r"((a)[0]), "r"((a)[1]), "r"((a)[2]), "r"((a)[3]), "r"((b)[0]), "r"((b)[1]))

__device__ __forceinline__ uint32_t packh2(float x, float y) {
    __half2 h = __floats2half2_rn(x, y);
    return *(uint32_t*)&h;
}

__global__ void zero_stats_kernel() {
    int i = blockIdx.x*256 + threadIdx.x;
    if (i < 3*2*HIDC) g_stats[i] = 0.0;
}
__global__ void prep_w_kernel(const float* __restrict__ w1,
                              const float* __restrict__ w2,
                              const float* __restrict__ w3) {
    int o = blockIdx.x, k = threadIdx.x;
    g_W1h[o*CC + k] = __float2half_rn(w1[o*(CC+3) + 3 + k]);
    if (k < HIDC) {
        g_W2h[o*HIDC + k] = __float2half_rn(w2[o*HIDC + k]);
        g_W3h[o*HIDC + k] = __float2half_rn(w3[o*HIDC + k]);
    }
}

// ---------------- FPS (unchanged, passing) ----------------
__global__ __launch_bounds__(1024) void fps_kernel(
    const float* __restrict__ seed, const float* __restrict__ xyz,
    float* __restrict__ out)
{
    int b = blockIdx.x, t = threadIdx.x;
    int lane = t & 31, wid = t >> 5;
    __shared__ float s_cv[2][32], s_cx[2][32], s_cy[2][32], s_cz[2][32];
    __shared__ int   s_ci[2][32];
    __shared__ int   s_inds[NPQ];

    const float* sb = seed + (size_t)b*NN*3;
    float px[4], py[4], pz[4], dist[4];
#pragma unroll
    for (int j = 0; j < 4; j++) {
        int i = t + j*1024;
        px[j] = sb[i*3+0]; py[j] = sb[i*3+1]; pz[j] = sb[i*3+2];
        dist[j] = 1e10f;
    }
    if (t == 0) s_inds[0] = 0;
    float lx = sb[0], ly = sb[1], lz = sb[2];

    for (int it = 1; it < NPQ; ++it) {
        float bv = -1.0f; int bi = 0;
        float bx = 0.f, by = 0.f, bz = 0.f;
#pragma unroll
        for (int j = 0; j < 4; j++) {
            float dx = __fadd_rn(px[j], -lx);
            float dy = __fadd_rn(py[j], -ly);
            float dz = __fadd_rn(pz[j], -lz);
            float d  = __fadd_rn(__fadd_rn(__fmul_rn(dx,dx), __fmul_rn(dy,dy)),
                                 __fmul_rn(dz,dz));
            dist[j] = fminf(dist[j], d);
            if (dist[j] > bv) { bv = dist[j]; bi = t + j*1024;
                                bx = px[j]; by = py[j]; bz = pz[j]; }
        }
#pragma unroll
        for (int off = 16; off > 0; off >>= 1) {
            float ov = __shfl_xor_sync(0xffffffffu, bv, off);
            int   oi = __shfl_xor_sync(0xffffffffu, bi, off);
            float ox = __shfl_xor_sync(0xffffffffu, bx, off);
            float oy = __shfl_xor_sync(0xffffffffu, by, off);
            float oz = __shfl_xor_sync(0xffffffffu, bz, off);
            if (ov > bv || (ov == bv && oi < bi)) {
                bv = ov; bi = oi; bx = ox; by = oy; bz = oz;
            }
        }
        int buf = it & 1;
        if (lane == 0) {
            s_cv[buf][wid] = bv; s_ci[buf][wid] = bi;
            s_cx[buf][wid] = bx; s_cy[buf][wid] = by; s_cz[buf][wid] = bz;
        }
        __syncthreads();
        float v  = s_cv[buf][lane];
        int   ci = s_ci[buf][lane];
        int   sl = lane;
#pragma unroll
        for (int off = 16; off > 0; off >>= 1) {
            float ov = __shfl_xor_sync(0xffffffffu, v,  off);
            int   oi = __shfl_xor_sync(0xffffffffu, ci, off);
            int   os = __shfl_xor_sync(0xffffffffu, sl, off);
            if (ov > v || (ov == v && oi < ci)) { v = ov; ci = oi; sl = os; }
        }
        lx = s_cx[buf][sl]; ly = s_cy[buf][sl]; lz = s_cz[buf][sl];
        if (t == 0) s_inds[it] = ci;
    }
    __syncthreads();
    for (int i = t; i < NPQ; i += 1024) {
        int id = s_inds[i];
        out[OUT_INDS + b*NPQ + i] = (float)id;
        const float* xb = xyz + ((size_t)b*NN + id)*3;
        out[((size_t)b*NPQ + i)*3 + 0] = xb[0];
        out[((size_t)b*NPQ + i)*3 + 1] = xb[1];
        out[((size_t)b*NPQ + i)*3 + 2] = xb[2];
    }
}

// ---------------- Ball query: smem cloud, 4 q/warp, gated ballots ----------
__global__ __launch_bounds__(256) void bq2_kernel(
    const float* __restrict__ xyz, const float* __restrict__ out)
{
    __shared__ float sx[NN], sy[NN], sz[NN];
    int tid = threadIdx.x, lane = tid & 31, w = tid >> 5;
    int qbase = blockIdx.x * 32;
    int b = qbase >> 9;
    const float* xb = xyz + (size_t)b*NN*3;
    for (int i = tid; i < NN; i += 256) {
        sx[i] = xb[i*3+0]; sy[i] = xb[i*3+1]; sz[i] = xb[i*3+2];
    }
    __syncthreads();

    const float R2c = (float)(0.3*0.3);
    const float RAD = 0.3f;
    int q0 = qbase + w*4;
    float qx[4], qy[4], qz[4];
    int found[4], first[4];
#pragma unroll
    for (int j = 0; j < 4; j++) {
        qx[j] = out[(size_t)(q0+j)*3+0];
        qy[j] = out[(size_t)(q0+j)*3+1];
        qz[j] = out[(size_t)(q0+j)*3+2];
        found[j] = 0; first[j] = -1;
    }
    for (int s = 0; s < NN/32; s++) {
        int i = s*32 + lane;
        float x = sx[i], y = sy[i], z = sz[i];
        bool pr[4];
#pragma unroll
        for (int j = 0; j < 4; j++) {
            float dx = __fadd_rn(qx[j], -x);
            float dy = __fadd_rn(qy[j], -y);
            float dz = __fadd_rn(qz[j], -z);
            float d  = __fadd_rn(__fadd_rn(__fmul_rn(dx,dx), __fmul_rn(dy,dy)),
                                 __fmul_rn(dz,dz));
            pr[j] = (d < R2c) && (found[j] < NSAMP);
        }
        unsigned anym = __ballot_sync(0xffffffffu, pr[0]|pr[1]|pr[2]|pr[3]);
        if (anym) {
#pragma unroll
            for (int j = 0; j < 4; j++) {
                if (found[j] >= NSAMP) continue;
                unsigned mask = __ballot_sync(0xffffffffu, pr[j]);
                if (!mask) continue;
                if (first[j] < 0) first[j] = s*32 + __ffs(mask) - 1;
                if (pr[j]) {
                    int pos = found[j] + __popc(mask & ((1u << lane) - 1u));
                    if (pos < NSAMP) {
                        int qg = q0 + j;
                        g_idx[qg*NSAMP + pos] = i;
                        g_gxyz[((size_t)qg*NSAMP + pos)*3 + 0] = __fdiv_rn(__fadd_rn(x, -qx[j]), RAD);
                        g_gxyz[((size_t)qg*NSAMP + pos)*3 + 1] = __fdiv_rn(__fadd_rn(y, -qy[j]), RAD);
                        g_gxyz[((size_t)qg*NSAMP + pos)*3 + 2] = __fdiv_rn(__fadd_rn(z, -qz[j]), RAD);
                    }
                }
                found[j] += __popc(mask);
            }
            if (found[0] >= NSAMP && found[1] >= NSAMP &&
                found[2] >= NSAMP && found[3] >= NSAMP) break;
        }
    }
#pragma unroll
    for (int j = 0; j < 4; j++) {
        if (found[j] < NSAMP) {
            int fi = first[j];
            float x = sx[fi], y = sy[fi], z = sz[fi];
            float p0 = __fdiv_rn(__fadd_rn(x, -qx[j]), RAD);
            float p1 = __fdiv_rn(__fadd_rn(y, -qy[j]), RAD);
            float p2 = __fdiv_rn(__fadd_rn(z, -qz[j]), RAD);
            if (lane >= found[j] && lane < NSAMP) {
                int qg = q0 + j;
                g_idx[qg*NSAMP + lane] = fi;
                g_gxyz[((size_t)qg*NSAMP + lane)*3 + 0] = p0;
                g_gxyz[((size_t)qg*NSAMP + lane)*3 + 1] = p1;
                g_gxyz[((size_t)qg*NSAMP + lane)*3 + 2] = p2;
            }
        }
    }
}

// ---------------- GEMM1 fp16: PF[b,m,o] = sum_c feat[b,c,m] * W1[o,c] -------
// M=4096/batch, N=128, K=256. 128x128 tile, kb=32, 8 warps (2x4), warp 64x32.
__global__ __launch_bounds__(256) void gemm1_h(const float* __restrict__ feat)
{
    __shared__ uint32_t As[128*18];   // [m][k-pair], stride 18 words
    __shared__ uint32_t Bs[128*18];   // [n][k-pair]
    int b = blockIdx.z;
    int mBase = blockIdx.x*128;
    const float* A = feat + (size_t)b*CC*NN;
    const uint32_t* W32 = (const uint32_t*)g_W1h;
    float* C = g_PF + ((size_t)b*NN + mBase)*HIDC;
    int tid = threadIdx.x;
    int lane = tid & 31, wid = tid >> 5;
    int wm = wid >> 2, wn = wid & 3;
    int lq = lane >> 2, lr = lane & 3;

    float c[4][4][4];
#pragma unroll
    for (int i = 0; i < 4; i++)
#pragma unroll
        for (int j = 0; j < 4; j++)
#pragma unroll
            for (int r = 0; r < 4; r++) c[i][j][r] = 0.f;

    for (int kb = 0; kb < CC/32; kb++) {
        // A: transpose-pack [k][m] f32 -> [m][k] fp16 pairs
#pragma unroll
        for (int r = 0; r < 2; r++) {
            int p = tid + 256*r;
            int cp = p >> 5, m4 = p & 31;
            const float* a0 = A + (size_t)(kb*32 + 2*cp)*NN + mBase + m4*4;
            float4 va = *(const float4*)a0;
            float4 vb = *(const float4*)(a0 + NN);
            As[(m4*4+0)*18 + cp] = packh2(va.x, vb.x);
            As[(m4*4+1)*18 + cp] = packh2(va.y, vb.y);
            As[(m4*4+2)*18 + cp] = packh2(va.z, vb.z);
            As[(m4*4+3)*18 + cp] = packh2(va.w, vb.w);
        }
        // B: copy fp16 pairs [n][256/2]
#pragma unroll
        for (int r = 0; r < 8; r++) {
            int p = tid + 256*r;
            int n = p >> 4, wd = p & 15;
            Bs[n*18 + wd] = W32[n*(CC/2) + kb*16 + wd];
        }
        __syncthreads();
#pragma unroll
        for (int ks = 0; ks < 2; ks++) {
            int k0 = ks*8;
            uint32_t af[4][4], bf[4][2];
#pragma unroll
            for (int mi = 0; mi < 4; mi++) {
                int m0 = wm*64 + mi*16;
                af[mi][0] = As[(m0 + lq    )*18 + k0 + lr    ];
                af[mi][1] = As[(m0 + 8 + lq)*18 + k0 + lr    ];
                af[mi][2] = As[(m0 + lq    )*18 + k0 + lr + 4];
                af[mi][3] = As[(m0 + 8 + lq)*18 + k0 + lr + 4];
            }
#pragma unroll
            for (int nj = 0; nj < 4; nj++) {
                int n0 = wn*32 + nj*8;
                bf[nj][0] = Bs[(n0+lq)*18 + k0 + lr    ];
                bf[nj][1] = Bs[(n0+lq)*18 + k0 + lr + 4];
            }
#pragma unroll
            for (int mi = 0; mi < 4; mi++)
#pragma unroll
                for (int nj = 0; nj < 4; nj++)
                    MMAH(c[mi][nj], af[mi], bf[nj]);
        }
        __syncthreads();
    }
#pragma unroll
    for (int mi = 0; mi < 4; mi++) {
#pragma unroll
        for (int nj = 0; nj < 4; nj++) {
            int gr  = wm*64 + mi*16 + lq;
            int col = wn*32 + nj*8 + 2*lr;
            *(float2*)(C + (size_t)gr*HIDC + col)     = make_float2(c[mi][nj][0], c[mi][nj][1]);
            *(float2*)(C + (size_t)(gr+8)*HIDC + col) = make_float2(c[mi][nj][2], c[mi][nj][3]);
        }
    }
}

// ---------------- assemble (unchanged, passing) ----------------
__global__ __launch_bounds__(256) void assemble_kernel(const float* __restrict__ w1)
{
    __shared__ float s_wx[HIDC], s_wy[HIDC], s_wz[HIDC];
    __shared__ float s_sum[HIDC], s_sq[HIDC];
    int tid = threadIdx.x, lane = tid & 31, w = tid >> 5;
    if (tid < HIDC) {
        s_wx[tid] = w1[tid*(CC+3) + 0];
        s_wy[tid] = w1[tid*(CC+3) + 1];
        s_wz[tid] = w1[tid*(CC+3) + 2];
        s_sum[tid] = 0.f; s_sq[tid] = 0.f;
    }
    __syncthreads();

    float ls[4] = {0,0,0,0}, lqa[4] = {0,0,0,0};
    float wx[4], wy[4], wz[4];
#pragma unroll
    for (int j = 0; j < 4; j++) {
        int o = lane*4 + j;
        wx[j] = s_wx[o]; wy[j] = s_wy[o]; wz[j] = s_wz[o];
    }
    for (int i = 0; i < 16; i++) {
        int p = blockIdx.x*128 + w*16 + i;
        int b = p >> 13;
        int n = g_idx[p];
        float gx = g_gxyz[(size_t)p*3+0];
        float gy = g_gxyz[(size_t)p*3+1];
        float gz = g_gxyz[(size_t)p*3+2];
        float4 v = *(const float4*)(g_PF + ((size_t)b*NN + n)*HIDC + lane*4);
        float y[4] = {v.x, v.y, v.z, v.w};
#pragma unroll
        for (int j = 0; j < 4; j++) {
            float r = y[j] + wx[j]*gx + wy[j]*gy + wz[j]*gz;
            y[j] = r;
            ls[j] += r; lqa[j] += r*r;
        }
        *(float4*)(g_Y1 + (size_t)p*HIDC + lane*4) = make_float4(y[0],y[1],y[2],y[3]);
    }
#pragma unroll
    for (int j = 0; j < 4; j++) {
        atomicAdd(&s_sum[lane*4 + j], ls[j]);
        atomicAdd(&s_sq [lane*4 + j], lqa[j]);
    }
    __syncthreads();
    if (tid < HIDC)      atomicAdd(&g_stats[0*256 + tid], (double)s_sum[tid]);
    else if (tid < 256)  atomicAdd(&g_stats[0*256 + 128 + (tid-128)], (double)s_sq[tid-128]);
}

__global__ void finalize_bn_kernel(int L, const float* __restrict__ g,
                                   const float* __restrict__ be)
{
    int cc = threadIdx.x;
    if (cc >= HIDC) return;
    const double cnt = (double)NPIX;
    double s = g_stats[L*256 + cc];
    double q = g_stats[L*256 + 128 + cc];
    double m = s / cnt;
    double v = q / cnt - m*m;
    if (v < 0.0) v = 0.0;
    float scale = g[cc] / sqrtf((float)v + 1e-5f);
    g_bn[L*384 + cc]       = (float)m;
    g_bn[L*384 + 128 + cc] = scale;
    g_bn[L*384 + 256 + cc] = be[cc];
}

// ---------------- NT GEMM fp16; layer 2 fuses maxpool ----------------
__global__ __launch_bounds__(256) void gemm_nt_h(int layer)
{
    __shared__ uint32_t As[128*18];
    __shared__ uint32_t Bs[128*18];
    __shared__ float s_bnp[384];
    __shared__ float s_sum[HIDC], s_sq[HIDC];
    const float* A  = (layer == 1) ? g_Y1 : g_Y2;
    const uint32_t* W32 = (const uint32_t*)((layer == 1) ? g_W2h : g_W3h);
    const float* bnp = g_bn + (layer-1)*384;

    int tid = threadIdx.x;
    int lane = tid & 31, wid = tid >> 5;
    int wm = wid >> 2, wn = wid & 3;
    int lq = lane >> 2, lr = lane & 3;
    if (tid < HIDC) { s_sum[tid] = 0.f; s_sq[tid] = 0.f; }
    for (int i = tid; i < 384; i += 256) s_bnp[i] = bnp[i];
    __syncthreads();

    size_t mBase = (size_t)blockIdx.x * 128;
    float c[4][4][4];
#pragma unroll
    for (int i = 0; i < 4; i++)
#pragma unroll
        for (int j = 0; j < 4; j++)
#pragma unroll
            for (int r = 0; r < 4; r++) c[i][j][r] = 0.f;

    for (int kb = 0; kb < 4; kb++) {
        // A: BN+ReLU fold, f32 -> fp16 pairs, [m][k]
#pragma unroll
        for (int r = 0; r < 4; r++) {
            int p = tid + 256*r;
            int row = p >> 3, kq = p & 7;
            int ch = kb*32 + kq*4;
            float4 v = *(const float4*)(A + (mBase + row)*HIDC + ch);
            float a0 = fmaxf(0.f, (v.x - s_bnp[ch+0])*s_bnp[128+ch+0] + s_bnp[256+ch+0]);
            float a1 = fmaxf(0.f, (v.y - s_bnp[ch+1])*s_bnp[128+ch+1] + s_bnp[256+ch+1]);
            float a2 = fmaxf(0.f, (v.z - s_bnp[ch+2])*s_bnp[128+ch+2] + s_bnp[256+ch+2]);
            float a3 = fmaxf(0.f, (v.w - s_bnp[ch+3])*s_bnp[128+ch+3] + s_bnp[256+ch+3]);
            As[row*18 + kq*2]     = packh2(a0, a1);
            As[row*18 + kq*2 + 1] = packh2(a2, a3);
        }
        // B: copy fp16 pairs [n][128/2]
#pragma unroll
        for (int r = 0; r < 8; r++) {
            int p = tid + 256*r;
            int n = p >> 4, wd = p & 15;
            Bs[n*18 + wd] = W32[n*(HIDC/2) + kb*16 + wd];
        }
        __syncthreads();
#pragma unroll
        for (int ks = 0; ks < 2; ks++) {
            int k0 = ks*8;
            uint32_t af[4][4], bf[4][2];
#pragma unroll
            for (int mi = 0; mi < 4; mi++) {
                int m0 = wm*64 + mi*16;
                af[mi][0] = As[(m0 + lq    )*18 + k0 + lr    ];
                af[mi][1] = As[(m0 + 8 + lq)*18 + k0 + lr    ];
                af[mi][2] = As[(m0 + lq    )*18 + k0 + lr + 4];
                af[mi][3] = As[(m0 + 8 + lq)*18 + k0 + lr + 4];
            }
#pragma unroll
            for (int nj = 0; nj < 4; nj++) {
                int n0 = wn*32 + nj*8;
                bf[nj][0] = Bs[(n0+lq)*18 + k0 + lr    ];
                bf[nj][1] = Bs[(n0+lq)*18 + k0 + lr + 4];
            }
#pragma unroll
            for (int mi = 0; mi < 4; mi++)
#pragma unroll
                for (int nj = 0; nj < 4; nj++)
                    MMAH(c[mi][nj], af[mi], bf[nj]);
        }
        __syncthreads();
    }
    if (layer == 1) {
#pragma unroll
        for (int mi = 0; mi < 4; mi++)
#pragma unroll
            for (int nj = 0; nj < 4; nj++) {
                size_t gr = mBase + wm*64 + mi*16 + lq;
                int col = wn*32 + nj*8 + 2*lr;
                *(float2*)(g_Y2 + gr*HIDC + col)     = make_float2(c[mi][nj][0], c[mi][nj][1]);
                *(float2*)(g_Y2 + (gr+8)*HIDC + col) = make_float2(c[mi][nj][2], c[mi][nj][3]);
            }
    } else {
#pragma unroll
        for (int mi = 0; mi < 4; mi++) {
            int qg = blockIdx.x*8 + wm*4 + mi;
#pragma unroll
            for (int nj = 0; nj < 4; nj++) {
                float m0v = fmaxf(c[mi][nj][0], c[mi][nj][2]);
                float m1v = fmaxf(c[mi][nj][1], c[mi][nj][3]);
#pragma unroll
                for (int o = 4; o <= 16; o <<= 1) {
                    m0v = fmaxf(m0v, __shfl_xor_sync(0xffffffffu, m0v, o));
                    m1v = fmaxf(m1v, __shfl_xor_sync(0xffffffffu, m1v, o));
                }
                if (lq == 0) {
                    int col = wn*32 + nj*8 + 2*lr;
                    *(float2*)(g_MX + (size_t)qg*HIDC + col) = make_float2(m0v, m1v);
                }
            }
        }
    }
#pragma unroll
    for (int nj = 0; nj < 4; nj++) {
        int ch = wn*32 + nj*8 + 2*lr;
        float s0 = 0.f, q0 = 0.f, s1 = 0.f, q1 = 0.f;
#pragma unroll
        for (int mi = 0; mi < 4; mi++) {
            float x;
            x = c[mi][nj][0]; s0 += x; q0 += x*x;
            x = c[mi][nj][2]; s0 += x; q0 += x*x;
            x = c[mi][nj][1]; s1 += x; q1 += x*x;
            x = c[mi][nj][3]; s1 += x; q1 += x*x;
        }
        atomicAdd(&s_sum[ch],   s0); atomicAdd(&s_sq[ch],   q0);
        atomicAdd(&s_sum[ch+1], s1); atomicAdd(&s_sq[ch+1], q1);
    }
    __syncthreads();
    if (tid < HIDC)      atomicAdd(&g_stats[layer*256 + tid], (double)s_sum[tid]);
    else if (tid < 256)  atomicAdd(&g_stats[layer*256 + 128 + (tid-128)], (double)s_sq[tid-128]);
}

// ---------------- BN3+ReLU on g_MX + transpose (unchanged) ----------------
__global__ __launch_bounds__(256) void maxfinal_kernel(float* __restrict__ out)
{
    __shared__ float T[HIDC][33];
    int b = blockIdx.x >> 4, pb = blockIdx.x & 15;
    int tid = threadIdx.x;
    const float* bnp = g_bn + 2*384;
#pragma unroll
    for (int r = 0; r < 16; r++) {
        int idx = tid + 256*r;
        int ql = idx >> 7, c = idx & 127;
        float v = g_MX[((size_t)(b*NPQ + pb*32 + ql))*HIDC + c];
        T[c][ql] = fmaxf(0.f, (v - bnp[c])*bnp[128+c] + bnp[256+c]);
    }
    __syncthreads();
#pragma unroll
    for (int r = 0; r < 16; r++) {
        int flat = tid + 256*r;
        int o = flat >> 5, pl = flat & 31;
        out[OUT_FEAT + (size_t)b*(HIDC*NPQ) + (size_t)o*NPQ + pb*32 + pl] = T[o][pl];
    }
}

// ---------------------------------------------------------------------------
extern "C" void kernel_launch(void* const* d_in, const int* in_sizes, int n_in,
                              void* d_out, int out_size)
{
    const float* xyz  = (const float*)d_in[0];
    const float* feat = (const float*)d_in[1];
    const float* seed = (const float*)d_in[2];
    const float* w1   = (const float*)d_in[3];
    const float* g1   = (const float*)d_in[4];
    const float* be1  = (const float*)d_in[5];
    const float* w2   = (const float*)d_in[6];
    const float* g2   = (const float*)d_in[7];
    const float* be2  = (const float*)d_in[8];
    const float* w3   = (const float*)d_in[9];
    const float* g3   = (const float*)d_in[10];
    const float* be3  = (const float*)d_in[11];
    float* out = (float*)d_out;

    zero_stats_kernel<<<3, 256>>>();
    prep_w_kernel<<<HIDC, CC>>>(w1, w2, w3);
    fps_kernel<<<BB, 1024>>>(seed, xyz, out);
    bq2_kernel<<<(BB*NPQ)/32, 256>>>(xyz, out);
    gemm1_h<<<dim3(NN/128, 1, BB), 256>>>(feat);
    assemble_kernel<<<NPIX/128, 256>>>(w1);
    finalize_bn_kernel<<<1, 128>>>(0, g1, be1);
    gemm_nt_h<<<NPIX/128, 256>>>(1);
    finalize_bn_kernel<<<1, 128>>>(1, g2, be2);
    gemm_nt_h<<<NPIX/128, 256>>>(2);
    finalize_bn_kernel<<<1, 128>>>(2, g3, be3);
    maxfinal_kernel<<<BB*16, 256>>>(out);
}